// round 2
// baseline (speedup 1.0000x reference)
#include <cuda_runtime.h>

#define GRID     128
#define NTHREADS 256
#define NT       4096     // B*S tokens

// ---- device globals (no allocation allowed) ----
__device__ float g_QKV[NT * 192];      // 3 MB
__device__ float g_A[NT * 64];         // 1 MB
__device__ float g_TEMB[4096 * 64];    // temb per step (supports up to 4096 loops)
__device__ unsigned g_arrive;
__device__ volatile unsigned g_release;

// ---- smem layout (floats) ----
#define OFF_WQKV 0            // 64*192 = 12288
#define OFF_WO   12288        // 64*64  = 4096
#define OFF_WFC  16384        // 64*256 = 16384
#define OFF_WPR  32768        // 256*64 = 16384
#define OFF_BIAS 49152        // 960
#define OFF_X    50112        // 32*64 = 2048
#define OFF_R    52160        // 5376 scratch (K/V tiles, softmax P, h/hid)
#define SMEM_FLOATS 57536
#define SMEM_BYTES (SMEM_FLOATS * 4)   // 230144 <= 232448

__device__ __forceinline__ void grid_sync(unsigned gen) {
    __syncthreads();
    if (threadIdx.x == 0) {
        __threadfence();
        unsigned prev = atomicAdd(&g_arrive, 1u);
        if (prev == gen * GRID - 1u) {
            __threadfence();
            g_release = gen;                       // volatile store
        } else {
            while (*(volatile unsigned*)&g_release < gen) { __nanosleep(64); }
        }
        __threadfence();
    }
    __syncthreads();
}

extern "C" __global__ void __launch_bounds__(NTHREADS, 1)
lt37349035606833_kernel(
    const int*   __restrict__ idx,   const int*   __restrict__ nloops_p,
    const float* __restrict__ wte,   const float* __restrict__ wpe,
    const float* __restrict__ tw1,   const float* __restrict__ tb1,
    const float* __restrict__ tw2,   const float* __restrict__ tb2,
    const float* __restrict__ ln1g_, const float* __restrict__ ln1b_,
    const float* __restrict__ wqkv_, const float* __restrict__ bqkv_,
    const float* __restrict__ wo_,   const float* __restrict__ bo_,
    const float* __restrict__ ln2g_, const float* __restrict__ ln2b_,
    const float* __restrict__ wfc_,  const float* __restrict__ bfc_,
    const float* __restrict__ wpr_,  const float* __restrict__ bpr_,
    const float* __restrict__ lnfg_, const float* __restrict__ lnfb_,
    float* __restrict__ out)
{
    extern __shared__ float sm[];
    const int tid = threadIdx.x;
    const int blk = blockIdx.x;
    const int w = tid >> 5, l = tid & 31;
    const int nloops = *nloops_p;
    unsigned gen = g_release;          // generation base (persists across graph replays)

    // ---- stage all weights/biases into smem ----
    for (int i = tid; i < 12288; i += NTHREADS) sm[OFF_WQKV + i] = wqkv_[i];
    for (int i = tid; i < 4096;  i += NTHREADS) sm[OFF_WO   + i] = wo_[i];
    for (int i = tid; i < 16384; i += NTHREADS) sm[OFF_WFC  + i] = wfc_[i];
    for (int i = tid; i < 16384; i += NTHREADS) sm[OFF_WPR  + i] = wpr_[i];
    if (tid < 192) sm[OFF_BIAS + tid] = bqkv_[tid];
    sm[OFF_BIAS + 256 + tid] = bfc_[tid];                 // 256 entries, tid<256 always
    if (tid < 64) {
        sm[OFF_BIAS + 192 + tid] = bo_[tid];
        sm[OFF_BIAS + 512 + tid] = bpr_[tid];
        sm[OFF_BIAS + 576 + tid] = ln1g_[tid];
        sm[OFF_BIAS + 640 + tid] = ln1b_[tid];
        sm[OFF_BIAS + 704 + tid] = ln2g_[tid];
        sm[OFF_BIAS + 768 + tid] = ln2b_[tid];
        sm[OFF_BIAS + 832 + tid] = lnfg_[tid];
        sm[OFF_BIAS + 896 + tid] = lnfb_[tid];
    }

    // ---- initial x tile: wte[idx] + wpe ----
    const int t0 = blk * 32;
    for (int i = tid; i < 2048; i += NTHREADS) {
        int t = i >> 6, d = i & 63;
        int tok = t0 + t;
        sm[OFF_X + i] = wte[idx[tok] * 64 + d] + wpe[(tok & 127) * 64 + d];
    }
    __syncthreads();

    // ---- precompute temb for every step (block s computes step s, s+128, ...) ----
    float* sR = sm + OFF_R;
    for (int s = blk; s < nloops; s += GRID) {
        float tt = (float)s;
        if (tid < 128) {
            float f = __expf(-9.2103403719761836f * (float)tid / 128.0f);
            float a = tt * f;
            sR[tid]       = cosf(a);
            sR[128 + tid] = sinf(a);
        }
        __syncthreads();
        for (int j = tid; j < 1024; j += NTHREADS) {
            float z = tb1[j];
            for (int k = 0; k < 256; ++k) z += sR[k] * tw1[k * 1024 + j];
            sR[256 + j] = z / (1.0f + __expf(-z));        // silu
        }
        __syncthreads();
        if (tid < 64) {
            float z = tb2[tid];
            for (int k = 0; k < 1024; ++k) z += sR[256 + k] * tw2[k * 64 + tid];
            g_TEMB[s * 64 + tid] = z;
        }
        __syncthreads();
    }
    grid_sync(++gen);

    const int bb = blk >> 2, hh = blk & 3;
    const int tbatt = bb * 128;
    float* sX  = sm + OFF_X;
    const float* sWq = sm + OFF_WQKV;
    const float* sWo = sm + OFF_WO;
    const float* sWf = sm + OFF_WFC;
    const float* sWp = sm + OFF_WPR;
    const float* sBq = sm + OFF_BIAS;
    const float* sBo = sm + OFF_BIAS + 192;
    const float* sBf = sm + OFF_BIAS + 256;
    const float* sBp = sm + OFF_BIAS + 512;
    const float* sL1g = sm + OFF_BIAS + 576, *sL1b = sm + OFF_BIAS + 640;
    const float* sL2g = sm + OFF_BIAS + 704, *sL2b = sm + OFF_BIAS + 768;
    const float* sLfg = sm + OFF_BIAS + 832, *sLfb = sm + OFF_BIAS + 896;

    for (int it = 0; it < nloops; ++it) {
        // ================= Phase A: x += temb; LN1; QKV =================
        {
            float* hA = sR + w * 256;
            const float* temb = g_TEMB + it * 64;
            #pragma unroll
            for (int t = 0; t < 4; ++t) {
                int lt = w * 4 + t;
                float x0 = sX[lt * 64 + l]      + temb[l];
                float x1 = sX[lt * 64 + 32 + l] + temb[32 + l];
                sX[lt * 64 + l]      = x0;
                sX[lt * 64 + 32 + l] = x1;
                float s1 = x0 + x1, s2 = x0 * x0 + x1 * x1;
                #pragma unroll
                for (int o = 16; o; o >>= 1) {
                    s1 += __shfl_xor_sync(0xffffffffu, s1, o);
                    s2 += __shfl_xor_sync(0xffffffffu, s2, o);
                }
                float mu = s1 * (1.0f / 64.0f);
                float rs = rsqrtf(s2 * (1.0f / 64.0f) - mu * mu + 1e-5f);
                hA[t * 64 + l]      = (x0 - mu) * rs * sL1g[l]      + sL1b[l];
                hA[t * 64 + 32 + l] = (x1 - mu) * rs * sL1g[32 + l] + sL1b[32 + l];
            }
            __syncwarp();
            float acc[6][4];
            #pragma unroll
            for (int s2 = 0; s2 < 6; ++s2)
                #pragma unroll
                for (int t = 0; t < 4; ++t) acc[s2][t] = 0.f;
            #pragma unroll 4
            for (int k = 0; k < 64; ++k) {
                float h0 = hA[k], h1v = hA[64 + k], h2 = hA[128 + k], h3 = hA[192 + k];
                #pragma unroll
                for (int s2 = 0; s2 < 6; ++s2) {
                    float wv = sWq[k * 192 + 32 * s2 + l];
                    acc[s2][0] += wv * h0; acc[s2][1] += wv * h1v;
                    acc[s2][2] += wv * h2; acc[s2][3] += wv * h3;
                }
            }
            #pragma unroll
            for (int t = 0; t < 4; ++t) {
                int tok = t0 + w * 4 + t;
                #pragma unroll
                for (int s2 = 0; s2 < 6; ++s2)
                    g_QKV[tok * 192 + 32 * s2 + l] = acc[s2][t] + sBq[32 * s2 + l];
            }
        }
        grid_sync(++gen);

        // ================= Phase B: attention for (bb, hh) =================
        // stage K,V (pitch 17 to kill bank conflicts); reads MUST bypass L1 (.cg)
        for (int i = tid; i < 2048; i += NTHREADS) {
            int kt = i >> 4, d = i & 15;
            sR[kt * 17 + d]        = __ldcg(&g_QKV[(tbatt + kt) * 192 + 64  + hh * 16 + d]);
            sR[2176 + kt * 17 + d] = __ldcg(&g_QKV[(tbatt + kt) * 192 + 128 + hh * 16 + d]);
        }
        __syncthreads();
        {
            float* sP = sR + 4352 + w * 128;
            for (int r = 0; r < 16; ++r) {
                int qt = w * 16 + r;
                const float* qptr = g_QKV + (tbatt + qt) * 192 + hh * 16;
                float q[16];
                #pragma unroll
                for (int d = 0; d < 16; ++d) q[d] = __ldcg(qptr + d);
                float sc0 = 0.f, sc1 = 0.f, sc2 = 0.f, sc3 = 0.f;
                #pragma unroll
                for (int d = 0; d < 16; ++d) {
                    sc0 += q[d] * sR[l * 17 + d];
                    sc1 += q[d] * sR[(l + 32) * 17 + d];
                    sc2 += q[d] * sR[(l + 64) * 17 + d];
                    sc3 += q[d] * sR[(l + 96) * 17 + d];
                }
                sc0 = sc0 * 0.25f + ((l      <= qt) ? 0.f : -1e9f);
                sc1 = sc1 * 0.25f + ((l + 32 <= qt) ? 0.f : -1e9f);
                sc2 = sc2 * 0.25f + ((l + 64 <= qt) ? 0.f : -1e9f);
                sc3 = sc3 * 0.25f + ((l + 96 <= qt) ? 0.f : -1e9f);
                float mx = fmaxf(fmaxf(sc0, sc1), fmaxf(sc2, sc3));
                #pragma unroll
                for (int o = 16; o; o >>= 1) mx = fmaxf(mx, __shfl_xor_sync(0xffffffffu, mx, o));
                float e0 = __expf(sc0 - mx), e1 = __expf(sc1 - mx);
                float e2 = __expf(sc2 - mx), e3 = __expf(sc3 - mx);
                float es = e0 + e1 + e2 + e3;
                #pragma unroll
                for (int o = 16; o; o >>= 1) es += __shfl_xor_sync(0xffffffffu, es, o);
                float inv = 1.0f / es;
                sP[l]      = e0 * inv;
                sP[l + 32] = e1 * inv;
                sP[l + 64] = e2 * inv;
                sP[l + 96] = e3 * inv;
                __syncwarp();
                int d = l & 15, half = l >> 4;
                const float* Vh = sR + 2176 + half * 64 * 17;
                const float* Ph = sP + half * 64;
                float ov = 0.f;
                #pragma unroll 8
                for (int k2 = 0; k2 < 64; ++k2) ov += Ph[k2] * Vh[k2 * 17 + d];
                ov += __shfl_xor_sync(0xffffffffu, ov, 16);
                if (half == 0) g_A[(tbatt + qt) * 64 + hh * 16 + d] = ov;
                __syncwarp();
            }
        }
        grid_sync(++gen);

        // ================= Phase C: o-proj + LN2 + MLP =================
        {
            float* hW = sR + w * 640;   // h[2][64] @0, hid[2][256] @128
            #pragma unroll
            for (int gp = 0; gp < 2; ++gp) {
                int lta = w * 4 + gp * 2, ltb = lta + 1;
                const float* Aa = g_A + (t0 + lta) * 64;
                const float* Ab = g_A + (t0 + ltb) * 64;
                float o00 = 0, o01 = 0, o10 = 0, o11 = 0;
                #pragma unroll 4
                for (int k = 0; k < 64; ++k) {
                    float a0 = __ldcg(Aa + k), a1 = __ldcg(Ab + k);   // bypass stale L1
                    float w0 = sWo[k * 64 + l], w1 = sWo[k * 64 + 32 + l];
                    o00 += w0 * a0; o01 += w0 * a1; o10 += w1 * a0; o11 += w1 * a1;
                }
                float xa0 = sX[lta * 64 + l]      + 0.1f * (o00 + sBo[l]);
                float xa1 = sX[lta * 64 + 32 + l] + 0.1f * (o10 + sBo[32 + l]);
                float xb0 = sX[ltb * 64 + l]      + 0.1f * (o01 + sBo[l]);
                float xb1 = sX[ltb * 64 + 32 + l] + 0.1f * (o11 + sBo[32 + l]);
                float s1a = xa0 + xa1, s2a = xa0 * xa0 + xa1 * xa1;
                float s1b = xb0 + xb1, s2b = xb0 * xb0 + xb1 * xb1;
                #pragma unroll
                for (int o = 16; o; o >>= 1) {
                    s1a += __shfl_xor_sync(0xffffffffu, s1a, o);
                    s2a += __shfl_xor_sync(0xffffffffu, s2a, o);
                    s1b += __shfl_xor_sync(0xffffffffu, s1b, o);
                    s2b += __shfl_xor_sync(0xffffffffu, s2b, o);
                }
                float mua = s1a * (1.f/64.f), rsa = rsqrtf(s2a * (1.f/64.f) - mua * mua + 1e-5f);
                float mub = s1b * (1.f/64.f), rsb = rsqrtf(s2b * (1.f/64.f) - mub * mub + 1e-5f);
                hW[l]      = (xa0 - mua) * rsa * sL2g[l]      + sL2b[l];
                hW[32 + l] = (xa1 - mua) * rsa * sL2g[32 + l] + sL2b[32 + l];
                hW[64 + l] = (xb0 - mub) * rsb * sL2g[l]      + sL2b[l];
                hW[96 + l] = (xb1 - mub) * rsb * sL2g[32 + l] + sL2b[32 + l];
                __syncwarp();
                float fa[8][2];
                #pragma unroll
                for (int s2 = 0; s2 < 8; ++s2) { fa[s2][0] = 0.f; fa[s2][1] = 0.f; }
                #pragma unroll 4
                for (int k = 0; k < 64; ++k) {
                    float h0 = hW[k], h1v = hW[64 + k];
                    #pragma unroll
                    for (int s2 = 0; s2 < 8; ++s2) {
                        float wv = sWf[k * 256 + 32 * s2 + l];
                        fa[s2][0] += wv * h0; fa[s2][1] += wv * h1v;
                    }
                }
                __syncwarp();
                #pragma unroll
                for (int s2 = 0; s2 < 8; ++s2) {
                    #pragma unroll
                    for (int t = 0; t < 2; ++t) {
                        float z = fa[s2][t] + sBf[32 * s2 + l];
                        float u = 0.7978845608028654f * (z + 0.044715f * z * z * z);
                        float e2u = __expf(2.0f * u);
                        float th = 1.0f - 2.0f / (e2u + 1.0f);   // tanh(u)
                        hW[128 + t * 256 + 32 * s2 + l] = 0.5f * z * (1.0f + th);
                    }
                }
                __syncwarp();
                float p00 = 0, p01 = 0, p10 = 0, p11 = 0;
                #pragma unroll 4
                for (int k = 0; k < 256; ++k) {
                    float h0 = hW[128 + k], h1v = hW[384 + k];
                    float w0 = sWp[k * 64 + l], w1 = sWp[k * 64 + 32 + l];
                    p00 += w0 * h0; p01 += w0 * h1v; p10 += w1 * h0; p11 += w1 * h1v;
                }
                sX[lta * 64 + l]      = xa0 + 0.1f * (p00 + sBp[l]);
                sX[lta * 64 + 32 + l] = xa1 + 0.1f * (p10 + sBp[32 + l]);
                sX[ltb * 64 + l]      = xb0 + 0.1f * (p01 + sBp[l]);
                sX[ltb * 64 + 32 + l] = xb1 + 0.1f * (p11 + sBp[32 + l]);
                __syncwarp();
            }
        }
        __syncthreads();   // sR (hW regions) must drain before next Phase A reuses sR
    }

    // ================= final LN -> out =================
    #pragma unroll
    for (int t = 0; t < 4; ++t) {
        int lt = w * 4 + t;
        float x0 = sX[lt * 64 + l], x1 = sX[lt * 64 + 32 + l];
        float s1 = x0 + x1, s2 = x0 * x0 + x1 * x1;
        #pragma unroll
        for (int o = 16; o; o >>= 1) {
            s1 += __shfl_xor_sync(0xffffffffu, s1, o);
            s2 += __shfl_xor_sync(0xffffffffu, s2, o);
        }
        float mu = s1 * (1.f/64.f);
        float rs = rsqrtf(s2 * (1.f/64.f) - mu * mu + 1e-5f);
        out[(t0 + lt) * 64 + l]      = (x0 - mu) * rs * sLfg[l]      + sLfb[l];
        out[(t0 + lt) * 64 + 32 + l] = (x1 - mu) * rs * sLfg[32 + l] + sLfb[32 + l];
    }
}

extern "C" void kernel_launch(void* const* d_in, const int* in_sizes, int n_in,
                              void* d_out, int out_size)
{
    (void)in_sizes; (void)n_in; (void)out_size;
    cudaFuncSetAttribute(lt37349035606833_kernel,
                         cudaFuncAttributeMaxDynamicSharedMemorySize, SMEM_BYTES);
    lt37349035606833_kernel<<<GRID, NTHREADS, SMEM_BYTES>>>(
        (const int*)  d_in[0],  (const int*)  d_in[1],
        (const float*)d_in[2],  (const float*)d_in[3],
        (const float*)d_in[4],  (const float*)d_in[5],
        (const float*)d_in[6],  (const float*)d_in[7],
        (const float*)d_in[8],  (const float*)d_in[9],
        (const float*)d_in[10], (const float*)d_in[11],
        (const float*)d_in[12], (const float*)d_in[13],
        (const float*)d_in[14], (const float*)d_in[15],
        (const float*)d_in[16], (const float*)d_in[17],
        (const float*)d_in[18], (const float*)d_in[19],
        (const float*)d_in[20], (const float*)d_in[21],
        (float*)d_out);
}